// round 5
// baseline (speedup 1.0000x reference)
#include <cuda_runtime.h>
#include <cuda_bf16.h>

#define B_DIM 32
#define T_DIM 1024
#define J_DIM 52
#define NBT (B_DIM * T_DIM)

// Convert one rot6d (6 floats) to a 3x3 rotation matrix, row-major,
// columns = (b1, b2, b3).
__device__ __forceinline__ void rot6d_to_mat(const float* __restrict__ v, float L[9]) {
    float a1x = v[0], a1y = v[1], a1z = v[2];
    float a2x = v[3], a2y = v[4], a2z = v[5];

    float n1 = a1x * a1x + a1y * a1y + a1z * a1z;
    float i1 = rsqrtf(fmaxf(n1, 1e-24f));
    float b1x = a1x * i1, b1y = a1y * i1, b1z = a1z * i1;

    float d = b1x * a2x + b1y * a2y + b1z * a2z;
    float ux = a2x - d * b1x;
    float uy = a2y - d * b1y;
    float uz = a2z - d * b1z;
    float n2 = ux * ux + uy * uy + uz * uz;
    float i2 = rsqrtf(fmaxf(n2, 1e-24f));
    float b2x = ux * i2, b2y = uy * i2, b2z = uz * i2;

    float b3x = b1y * b2z - b1z * b2y;
    float b3y = b1z * b2x - b1x * b2z;
    float b3z = b1x * b2y - b1y * b2x;

    L[0] = b1x; L[1] = b2x; L[2] = b3x;
    L[3] = b1y; L[4] = b2y; L[5] = b3y;
    L[6] = b1z; L[7] = b2z; L[8] = b3z;
}

// DFS over the binary-heap skeleton. j = joint index, d = depth (stack slot).
// gR[d-1] / ppos[d-1] hold the parent's global rotation / position.
template <int j, int d>
__device__ __forceinline__ void fk_node(const float* __restrict__ r6,
                                        float* __restrict__ o,
                                        float (&gR)[6][9],
                                        float (&ppos)[6][3],
                                        const float* __restrict__ rest) {
    float L[9];
    rot6d_to_mat(r6 + j * 6, L);

    // rest offset (warp-uniform -> L1 broadcast)
    float rx = __ldg(rest + j * 3 + 0);
    float ry = __ldg(rest + j * 3 + 1);
    float rz = __ldg(rest + j * 3 + 2);

    // local_rotated = L @ rest[j]
    float lr0 = L[0] * rx + L[1] * ry + L[2] * rz;
    float lr1 = L[3] * rx + L[4] * ry + L[5] * rz;
    float lr2 = L[6] * rx + L[7] * ry + L[8] * rz;

    // pos[j] = pos[p] + gR[p] @ lr
    float px = ppos[d - 1][0] + gR[d - 1][0] * lr0 + gR[d - 1][1] * lr1 + gR[d - 1][2] * lr2;
    float py = ppos[d - 1][1] + gR[d - 1][3] * lr0 + gR[d - 1][4] * lr1 + gR[d - 1][5] * lr2;
    float pz = ppos[d - 1][2] + gR[d - 1][6] * lr0 + gR[d - 1][7] * lr1 + gR[d - 1][8] * lr2;

    o[j * 3 + 0] = px;
    o[j * 3 + 1] = py;
    o[j * 3 + 2] = pz;

    if constexpr (2 * j + 1 < J_DIM) {
        // non-leaf: need gR[j] = gR[p] @ L
        ppos[d][0] = px; ppos[d][1] = py; ppos[d][2] = pz;
        #pragma unroll
        for (int i = 0; i < 3; i++) {
            float p0 = gR[d - 1][i * 3 + 0];
            float p1 = gR[d - 1][i * 3 + 1];
            float p2 = gR[d - 1][i * 3 + 2];
            gR[d][i * 3 + 0] = p0 * L[0] + p1 * L[3] + p2 * L[6];
            gR[d][i * 3 + 1] = p0 * L[1] + p1 * L[4] + p2 * L[7];
            gR[d][i * 3 + 2] = p0 * L[2] + p1 * L[5] + p2 * L[8];
        }
        fk_node<2 * j + 1, d + 1>(r6, o, gR, ppos, rest);
        if constexpr (2 * j + 2 < J_DIM) {
            fk_node<2 * j + 2, d + 1>(r6, o, gR, ppos, rest);
        }
    }
}

__global__ void __launch_bounds__(128)
fk_kernel(const float* __restrict__ rot6d,
          const float* __restrict__ trans,
          const float* __restrict__ yaw,
          const float* __restrict__ rest,
          float* __restrict__ out) {
    int bt = blockIdx.x * blockDim.x + threadIdx.x;
    if (bt >= NBT) return;

    const float* r6 = rot6d + (size_t)bt * J_DIM * 6;
    float* o = out + (size_t)bt * J_DIM * 3;

    float gR[6][9];
    float ppos[6][3];

    // Root: gR[0] = R_yaw @ local_R[0]; pos[0] = root_translation
    float L[9];
    rot6d_to_mat(r6, L);
    float sy, cy;
    __sincosf(yaw[bt], &sy, &cy);

    // R_yaw rows: [cy,0,sy], [0,1,0], [-sy,0,cy]
    gR[0][0] = cy * L[0] + sy * L[6];
    gR[0][1] = cy * L[1] + sy * L[7];
    gR[0][2] = cy * L[2] + sy * L[8];
    gR[0][3] = L[3];
    gR[0][4] = L[4];
    gR[0][5] = L[5];
    gR[0][6] = cy * L[6] - sy * L[0];
    gR[0][7] = cy * L[7] - sy * L[1];
    gR[0][8] = cy * L[8] - sy * L[2];

    float tx = trans[bt * 3 + 0];
    float ty = trans[bt * 3 + 1];
    float tz = trans[bt * 3 + 2];
    ppos[0][0] = tx; ppos[0][1] = ty; ppos[0][2] = tz;
    o[0] = tx; o[1] = ty; o[2] = tz;

    fk_node<1, 1>(r6, o, gR, ppos, rest);
    fk_node<2, 1>(r6, o, gR, ppos, rest);
}

extern "C" void kernel_launch(void* const* d_in, const int* in_sizes, int n_in,
                              void* d_out, int out_size) {
    const float* rot6d = (const float*)d_in[0];
    const float* trans = (const float*)d_in[1];
    const float* yaw   = (const float*)d_in[2];
    // d_in[3] = parents (int64) — tree is fixed at compile time, unused.
    const float* rest  = (const float*)d_in[4];
    float* out = (float*)d_out;

    dim3 block(128);
    dim3 grid((NBT + block.x - 1) / block.x);
    fk_kernel<<<grid, block>>>(rot6d, trans, yaw, rest, out);
}